// round 14
// baseline (speedup 1.0000x reference)
#include <cuda_runtime.h>
#include <cuda_fp16.h>
#include <math.h>
#include <stdint.h>

#define N 8192
#define D 1024
#define BM 128
#define BN 128
#define BK 64             // fp8 elems per k-chunk (64 B per row-chunk)
#define KSTEPS (D / BK)   // 16
#define NB (N / BM)       // 64 block-rows
#define NTRI (NB * (NB + 1) / 2)  // 2080 upper-tri blocks

// Scratch (__device__ globals: allocation-free rule)
__device__ uint8_t g_xq[(size_t)N * D];   // normalized rows, e4m3, 8 MB
__device__ float g_top[N];
__device__ float g_bot[N];
__device__ int   g_lab[N];
__device__ unsigned int g_cnt;

// ------------------------------ PTX helpers -------------------------------
__device__ __forceinline__ uint32_t smem_u32(const void* p) {
    uint32_t a;
    asm("{ .reg .u64 t; cvta.to.shared.u64 t, %1; cvt.u32.u64 %0, t; }"
        : "=r"(a) : "l"(p));
    return a;
}
#define CPA(dst, src) \
    asm volatile("cp.async.cg.shared.global [%0], [%1], 16;" :: "r"(dst), "l"(src) : "memory")
#define CPA_COMMIT() asm volatile("cp.async.commit_group;" ::: "memory")
#define CPA_WAIT0()  asm volatile("cp.async.wait_group 0;" ::: "memory")

#define LDX4(r, a) \
    asm volatile("ldmatrix.sync.aligned.m8n8.x4.shared.b16 {%0,%1,%2,%3}, [%4];" \
        : "=r"((r)[0]), "=r"((r)[1]), "=r"((r)[2]), "=r"((r)[3]) : "r"(a))

// fp8 e4m3 mma with f16 accumulators: d/c are 2x f16x2 registers
__device__ __forceinline__ void mma_fp8_h(uint32_t* d, const uint32_t* a, const uint32_t* b) {
    asm volatile(
        "mma.sync.aligned.m16n8k32.row.col.f16.e4m3.e4m3.f16 "
        "{%0,%1}, {%2,%3,%4,%5}, {%6,%7}, {%0,%1};"
        : "+r"(d[0]), "+r"(d[1])
        : "r"(a[0]), "r"(a[1]), "r"(a[2]), "r"(a[3]), "r"(b[0]), "r"(b[1]));
}

// ---------------------------------------------------------------------------
// Row normalization -> e4m3 unit rows. One WARP per row: pure shuffle reduce,
// no smem, no __syncthreads. Also zeroes top/bot accumulators.
// ---------------------------------------------------------------------------
__global__ void normalize_kernel(const float* __restrict__ x) {
    const int warp = threadIdx.x >> 5;
    const int lane = threadIdx.x & 31;
    const int row = blockIdx.x * 8 + warp;

    const float4* xr = reinterpret_cast<const float4*>(x + (size_t)row * D);
    float4 v[8];
    float ss = 0.0f;
    #pragma unroll
    for (int k = 0; k < 8; k++) {
        v[k] = xr[lane + 32 * k];
        ss += v[k].x * v[k].x + v[k].y * v[k].y + v[k].z * v[k].z + v[k].w * v[k].w;
    }
    #pragma unroll
    for (int o = 16; o; o >>= 1) ss += __shfl_xor_sync(0xffffffffu, ss, o);

    const float inv = 1.0f / fmaxf(sqrtf(ss), 1e-8f);
    uint32_t* dst = reinterpret_cast<uint32_t*>(g_xq + (size_t)row * D);
    #pragma unroll
    for (int k = 0; k < 8; k++) {
        uint16_t h0, h1;
        asm("cvt.rn.satfinite.e4m3x2.f32 %0, %1, %2;"
            : "=h"(h0) : "f"(v[k].y * inv), "f"(v[k].x * inv));
        asm("cvt.rn.satfinite.e4m3x2.f32 %0, %1, %2;"
            : "=h"(h1) : "f"(v[k].w * inv), "f"(v[k].z * inv));
        dst[lane + 32 * k] = (uint32_t)h0 | ((uint32_t)h1 << 16);
    }
    if (lane == 0) { g_top[row] = 0.0f; g_bot[row] = 0.0f; }
}

// ---------------------------------------------------------------------------
// Label conversion with int64/int32 auto-detection (labels in [0,10)).
// Also resets the snnl completion counter each run (graph-replay safe).
// ---------------------------------------------------------------------------
__global__ void labels_kernel(const int* __restrict__ y32) {
    __shared__ int odd_nonzero;
    int t = threadIdx.x;
    if (t == 0) odd_nonzero = 0;
    __syncthreads();
    if (t < 256 && y32[2 * t + 1] != 0) odd_nonzero = 1;
    __syncthreads();
    bool is64 = (odd_nonzero == 0);
    int i = blockIdx.x * blockDim.x + t;
    if (i < N) g_lab[i] = is64 ? y32[2 * i] : y32[i];
    if (i == 0) g_cnt = 0u;
}

// ---------------------------------------------------------------------------
// FP8 (f16-accum) MMA fused sim-GEMM + SNNL epilogue, upper-tri blocks only.
// 128 threads = 4 warps of 64x64 subtiles. EXACT R12/R8 mainloop (sequential
// K order — co-resident CTAs share L2 chunk loads constructively).
// Loss reduction fused into the last-finishing CTA.
// smem rows: 64 B, 16B-chunk XOR swizzle on (row>>1)&3.
// ---------------------------------------------------------------------------
__global__ void __launch_bounds__(128, 4)
snnl_fp8h(const float* __restrict__ Tptr, float* __restrict__ out) {
    __shared__ __align__(1024) uint8_t sA[2][BM * BK];
    __shared__ __align__(1024) uint8_t sB[2][BN * BK];
    __shared__ float rowsum[2 * BM];
    __shared__ float colsum[2 * BN];

    const int tid = threadIdx.x;
    const int wid = tid >> 5;
    const int lane = tid & 31;

    // triangular decode: blockIdx.x -> (bi, bj), bi <= bj
    int t = blockIdx.x, bi = 0, rem = NB;
    while (t >= rem) { t -= rem; bi++; rem--; }
    const int bj = bi + t;
    const bool diag = (bi == bj);
    const int i0 = bi * BM;
    const int j0 = bj * BN;

    const int wm = (wid >> 1) * 64;   // 0 / 64
    const int wn = (wid & 1) * 64;    // 0 / 64

    uint32_t aBase[2] = { smem_u32(&sA[0][0]), smem_u32(&sA[1][0]) };
    uint32_t bBase[2] = { smem_u32(&sB[0][0]), smem_u32(&sB[1][0]) };
    if (diag) { bBase[0] = aBase[0]; bBase[1] = aBase[1]; }

    // loader mapping: 128 threads x 4 row-groups cover 128 rows x 4 chunks
    const int lrow = tid >> 2;        // 0..31
    const int lch  = tid & 3;         // 16B chunk in 64B row
    const uint32_t loff = lrow * 64 + ((lch ^ ((lrow >> 1) & 3)) << 4);
    // rows p*32 + lrow have identical swizzle term -> offset + p*2048
    const uint8_t* Ag = g_xq + (size_t)(i0 + lrow) * D + lch * 16;
    const uint8_t* Bg = g_xq + (size_t)(j0 + lrow) * D + lch * 16;

    // ldmatrix per-lane address components
    uint32_t aoff[4], asw[4];
    #pragma unroll
    for (int mt = 0; mt < 4; mt++) {
        int r = wm + mt * 16 + ((lane >> 3) & 1) * 8 + (lane & 7);
        aoff[mt] = r * 64;
        asw[mt] = (r >> 1) & 3;
    }
    uint32_t boff[4], bsw[4];
    #pragma unroll
    for (int bt = 0; bt < 4; bt++) {
        int r = wn + bt * 16 + (lane >> 4) * 8 + (lane & 7);
        boff[bt] = r * 64;
        bsw[bt] = (r >> 1) & 3;
    }

    uint32_t acc[4][8][2];   // f16x2 accumulators (4 m-tiles x 8 n-tiles)
    #pragma unroll
    for (int a = 0; a < 4; a++)
        #pragma unroll
        for (int b = 0; b < 8; b++) { acc[a][b][0] = 0u; acc[a][b][1] = 0u; }

    // prologue: load chunk 0 into buffer 0
    #pragma unroll
    for (int p = 0; p < 4; p++) {
        CPA(aBase[0] + loff + p * 2048, Ag + (size_t)(p * 32) * D);
        if (!diag) CPA(bBase[0] + loff + p * 2048, Bg + (size_t)(p * 32) * D);
    }
    CPA_COMMIT();

    for (int kc = 0; kc < KSTEPS; kc++) {
        const int b = kc & 1;
        CPA_WAIT0();           // buffer b data arrived
        __syncthreads();       // visible to all; everyone done reading 1-b
        if (kc + 1 < KSTEPS) {
            const uint8_t* An = Ag + (kc + 1) * BK;
            const uint8_t* Bn = Bg + (kc + 1) * BK;
            #pragma unroll
            for (int p = 0; p < 4; p++) {
                CPA(aBase[1 - b] + loff + p * 2048, An + (size_t)(p * 32) * D);
                if (!diag) CPA(bBase[1 - b] + loff + p * 2048, Bn + (size_t)(p * 32) * D);
            }
            CPA_COMMIT();
        }

        #pragma unroll
        for (int ks = 0; ks < 2; ks++) {
            uint32_t af[4][4], bf[4][4];
            const uint32_t ca = 2 * ks + (lane >> 4);
            const uint32_t cb = 2 * ks + ((lane >> 3) & 1);
            #pragma unroll
            for (int mt = 0; mt < 4; mt++)
                LDX4(af[mt], aBase[b] + aoff[mt] + ((ca ^ asw[mt]) << 4));
            #pragma unroll
            for (int bt = 0; bt < 4; bt++)
                LDX4(bf[bt], bBase[b] + boff[bt] + ((cb ^ bsw[bt]) << 4));
            #pragma unroll
            for (int mt = 0; mt < 4; mt++)
                #pragma unroll
                for (int nt = 0; nt < 8; nt++)
                    mma_fp8_h(acc[mt][nt], af[mt], &bf[nt >> 1][(nt & 1) * 2]);
        }
    }
    __syncthreads();

    // ---------------- epilogue ----------------
    const float invT = 1.0f / Tptr[0];
    rowsum[tid] = 0.0f; rowsum[tid + 128] = 0.0f;
    colsum[tid] = 0.0f; colsum[tid + 128] = 0.0f;
    __syncthreads();

    const int g = lane >> 2, tig = lane & 3;
    int yj[8][2];
    #pragma unroll
    for (int nt = 0; nt < 8; nt++) {
        int j = j0 + wn + nt * 8 + 2 * tig;
        yj[nt][0] = g_lab[j];
        yj[nt][1] = g_lab[j + 1];
    }

    float ct[8][2] = {}, cb2[8][2] = {};   // per-thread column partials

    #pragma unroll
    for (int mt = 0; mt < 4; mt++) {
        #pragma unroll
        for (int h = 0; h < 2; h++) {
            const int li = wm + mt * 16 + h * 8 + g;
            const int i = i0 + li;
            const int yi = g_lab[i];
            float ts = 0.0f, bs = 0.0f;
            #pragma unroll
            for (int nt = 0; nt < 8; nt++) {
                float2 dv = __half22float2(
                    *reinterpret_cast<const __half2*>(&acc[mt][nt][h]));
                int j = j0 + wn + nt * 8 + 2 * tig;
                float f0 = __expf((dv.x - 1.0f) * invT);
                float f1 = __expf((dv.y - 1.0f) * invT);
                if (i == j) f0 = 0.0f;
                if (i == j + 1) f1 = 0.0f;
                bs += f0 + f1;
                cb2[nt][0] += f0;
                cb2[nt][1] += f1;
                if (yi == yj[nt][0]) { ts += f0; ct[nt][0] += f0; }
                if (yi == yj[nt][1]) { ts += f1; ct[nt][1] += f1; }
            }
            ts += __shfl_xor_sync(0xffffffffu, ts, 1);
            ts += __shfl_xor_sync(0xffffffffu, ts, 2);
            bs += __shfl_xor_sync(0xffffffffu, bs, 1);
            bs += __shfl_xor_sync(0xffffffffu, bs, 2);
            if (tig == 0) {
                atomicAdd(&rowsum[li * 2 + 0], ts);
                atomicAdd(&rowsum[li * 2 + 1], bs);
            }
        }
    }

    if (!diag) {
        #pragma unroll
        for (int nt = 0; nt < 8; nt++) {
            #pragma unroll
            for (int c = 0; c < 2; c++) {
                float vt = ct[nt][c], vb = cb2[nt][c];
                #pragma unroll
                for (int o = 4; o < 32; o <<= 1) {
                    vt += __shfl_xor_sync(0xffffffffu, vt, o);
                    vb += __shfl_xor_sync(0xffffffffu, vb, o);
                }
                if (g == 0) {
                    int lj = wn + nt * 8 + 2 * tig + c;
                    atomicAdd(&colsum[lj * 2 + 0], vt);
                    atomicAdd(&colsum[lj * 2 + 1], vb);
                }
            }
        }
    }

    __syncthreads();
    // 128 threads scatter 128 rows (and cols if off-diagonal)
    atomicAdd(&g_top[i0 + tid], rowsum[tid * 2 + 0]);
    atomicAdd(&g_bot[i0 + tid], rowsum[tid * 2 + 1]);
    if (!diag) {
        atomicAdd(&g_top[j0 + tid], colsum[tid * 2 + 0]);
        atomicAdd(&g_bot[j0 + tid], colsum[tid * 2 + 1]);
    }

    // ---------------- fused loss (last CTA to finish) ----------------
    __threadfence();
    __shared__ bool is_last;
    if (tid == 0)
        is_last = (atomicAdd(&g_cnt, 1u) == (unsigned)(NTRI - 1));
    __syncthreads();
    if (!is_last) return;
    __threadfence();   // all other CTAs' g_top/g_bot atomics are visible

    float s = 0.0f;
    #pragma unroll 4
    for (int i = tid; i < N; i += 128)
        s += __logf((g_top[i] + 1e-9f) / g_bot[i]);
    #pragma unroll
    for (int o = 16; o; o >>= 1) s += __shfl_xor_sync(0xffffffffu, s, o);
    if (lane == 0) rowsum[wid] = s;
    __syncthreads();
    if (tid == 0)
        out[0] = -(rowsum[0] + rowsum[1] + rowsum[2] + rowsum[3]) / (float)N;
}

extern "C" void kernel_launch(void* const* d_in, const int* in_sizes, int n_in,
                              void* d_out, int out_size) {
    const float* x = (const float*)d_in[0];
    const int*   y = (const int*)d_in[1];   // int32 view; layout auto-detected
    const float* T = (const float*)d_in[2];
    float* out = (float*)d_out;

    normalize_kernel<<<N / 8, 256>>>(x);    // 1
    labels_kernel<<<N / 256, 256>>>(y);     // 2
    snnl_fp8h<<<NTRI, 128>>>(T, out);       // 3 (loss fused into last CTA)
}

// round 15
// speedup vs baseline: 1.1216x; 1.1216x over previous
#include <cuda_runtime.h>
#include <cuda_fp16.h>
#include <math.h>
#include <stdint.h>

#define N 8192
#define D 1024
#define BM 128
#define BN 128
#define BK 64             // fp8 elems per k-chunk (64 B per row-chunk)
#define KSTEPS (D / BK)   // 16
#define NB (N / BM)       // 64 block-rows
#define NTRI (NB * (NB + 1) / 2)  // 2080 upper-tri blocks

// Scratch (__device__ globals: allocation-free rule)
__device__ uint8_t g_xq[(size_t)N * D];   // normalized rows, e4m3, 8 MB
__device__ float g_top[N];
__device__ float g_bot[N];
__device__ int   g_lab[N];
__device__ float g_loss;
__device__ unsigned int g_cnt;

// ------------------------------ PTX helpers -------------------------------
__device__ __forceinline__ uint32_t smem_u32(const void* p) {
    uint32_t a;
    asm("{ .reg .u64 t; cvta.to.shared.u64 t, %1; cvt.u32.u64 %0, t; }"
        : "=r"(a) : "l"(p));
    return a;
}
#define CPA(dst, src) \
    asm volatile("cp.async.cg.shared.global [%0], [%1], 16;" :: "r"(dst), "l"(src) : "memory")
#define CPA_COMMIT() asm volatile("cp.async.commit_group;" ::: "memory")
#define CPA_WAIT0()  asm volatile("cp.async.wait_group 0;" ::: "memory")

#define LDX4(r, a) \
    asm volatile("ldmatrix.sync.aligned.m8n8.x4.shared.b16 {%0,%1,%2,%3}, [%4];" \
        : "=r"((r)[0]), "=r"((r)[1]), "=r"((r)[2]), "=r"((r)[3]) : "r"(a))

// fp8 e4m3 mma with f16 accumulators: d/c are 2x f16x2 registers
__device__ __forceinline__ void mma_fp8_h(uint32_t* d, const uint32_t* a, const uint32_t* b) {
    asm volatile(
        "mma.sync.aligned.m16n8k32.row.col.f16.e4m3.e4m3.f16 "
        "{%0,%1}, {%2,%3,%4,%5}, {%6,%7}, {%0,%1};"
        : "+r"(d[0]), "+r"(d[1])
        : "r"(a[0]), "r"(a[1]), "r"(a[2]), "r"(a[3]), "r"(b[0]), "r"(b[1]));
}

// ---------------------------------------------------------------------------
// Row normalization -> e4m3 unit rows. One WARP per row: pure shuffle reduce,
// no smem, no __syncthreads. Also zeroes top/bot accumulators.
// ---------------------------------------------------------------------------
__global__ void normalize_kernel(const float* __restrict__ x) {
    const int warp = threadIdx.x >> 5;
    const int lane = threadIdx.x & 31;
    const int row = blockIdx.x * 8 + warp;

    const float4* xr = reinterpret_cast<const float4*>(x + (size_t)row * D);
    float4 v[8];
    float ss = 0.0f;
    #pragma unroll
    for (int k = 0; k < 8; k++) {
        v[k] = xr[lane + 32 * k];
        ss += v[k].x * v[k].x + v[k].y * v[k].y + v[k].z * v[k].z + v[k].w * v[k].w;
    }
    #pragma unroll
    for (int o = 16; o; o >>= 1) ss += __shfl_xor_sync(0xffffffffu, ss, o);

    const float inv = 1.0f / fmaxf(sqrtf(ss), 1e-8f);
    uint32_t* dst = reinterpret_cast<uint32_t*>(g_xq + (size_t)row * D);
    #pragma unroll
    for (int k = 0; k < 8; k++) {
        uint16_t h0, h1;
        asm("cvt.rn.satfinite.e4m3x2.f32 %0, %1, %2;"
            : "=h"(h0) : "f"(v[k].y * inv), "f"(v[k].x * inv));
        asm("cvt.rn.satfinite.e4m3x2.f32 %0, %1, %2;"
            : "=h"(h1) : "f"(v[k].w * inv), "f"(v[k].z * inv));
        dst[lane + 32 * k] = (uint32_t)h0 | ((uint32_t)h1 << 16);
    }
    if (lane == 0) { g_top[row] = 0.0f; g_bot[row] = 0.0f; }
    if (row == 0 && lane < 2) {
        // second init point for safety (labels_kernel also does it)
        if (lane == 0) g_loss = 0.0f; else g_cnt = 0u;
    }
}

// ---------------------------------------------------------------------------
// Label conversion with int64/int32 auto-detection (labels in [0,10)).
// Also resets the loss accumulator + completion counter each run.
// ---------------------------------------------------------------------------
__global__ void labels_kernel(const int* __restrict__ y32) {
    __shared__ int odd_nonzero;
    int t = threadIdx.x;
    if (t == 0) odd_nonzero = 0;
    __syncthreads();
    if (t < 256 && y32[2 * t + 1] != 0) odd_nonzero = 1;
    __syncthreads();
    bool is64 = (odd_nonzero == 0);
    int i = blockIdx.x * blockDim.x + t;
    if (i < N) g_lab[i] = is64 ? y32[2 * i] : y32[i];
    if (i == 0) { g_loss = 0.0f; g_cnt = 0u; }
}

// ---------------------------------------------------------------------------
// FP8 (f16-accum) MMA fused sim-GEMM + SNNL epilogue, upper-tri blocks only.
// 128 threads = 4 warps, each computing a 64x64 subtile (2x2 warp grid).
// Exact R8 configuration (best measured: 183 us main, rel_err 0.0).
// smem rows: 64 B, 16B-chunk XOR swizzle on (row>>1)&3.
// ---------------------------------------------------------------------------
__global__ void __launch_bounds__(128, 4)
snnl_fp8h(const float* __restrict__ Tptr) {
    __shared__ __align__(1024) uint8_t sA[2][BM * BK];
    __shared__ __align__(1024) uint8_t sB[2][BN * BK];
    __shared__ float rowsum[2 * BM];
    __shared__ float colsum[2 * BN];

    const int tid = threadIdx.x;
    const int wid = tid >> 5;
    const int lane = tid & 31;

    // triangular decode: blockIdx.x -> (bi, bj), bi <= bj
    int t = blockIdx.x, bi = 0, rem = NB;
    while (t >= rem) { t -= rem; bi++; rem--; }
    const int bj = bi + t;
    const bool diag = (bi == bj);
    const int i0 = bi * BM;
    const int j0 = bj * BN;

    const int wm = (wid >> 1) * 64;   // 0 / 64
    const int wn = (wid & 1) * 64;    // 0 / 64

    uint32_t aBase[2] = { smem_u32(&sA[0][0]), smem_u32(&sA[1][0]) };
    uint32_t bBase[2] = { smem_u32(&sB[0][0]), smem_u32(&sB[1][0]) };
    if (diag) { bBase[0] = aBase[0]; bBase[1] = aBase[1]; }

    // loader mapping: 128 threads x 4 row-groups cover 128 rows x 4 chunks
    const int lrow = tid >> 2;        // 0..31
    const int lch  = tid & 3;         // 16B chunk in 64B row
    const uint32_t loff = lrow * 64 + ((lch ^ ((lrow >> 1) & 3)) << 4);
    // rows p*32 + lrow have identical swizzle term -> offset + p*2048
    const uint8_t* Ag = g_xq + (size_t)(i0 + lrow) * D + lch * 16;
    const uint8_t* Bg = g_xq + (size_t)(j0 + lrow) * D + lch * 16;

    // ldmatrix per-lane address components
    uint32_t aoff[4], asw[4];
    #pragma unroll
    for (int mt = 0; mt < 4; mt++) {
        int r = wm + mt * 16 + ((lane >> 3) & 1) * 8 + (lane & 7);
        aoff[mt] = r * 64;
        asw[mt] = (r >> 1) & 3;
    }
    uint32_t boff[4], bsw[4];
    #pragma unroll
    for (int bt = 0; bt < 4; bt++) {
        int r = wn + bt * 16 + (lane >> 4) * 8 + (lane & 7);
        boff[bt] = r * 64;
        bsw[bt] = (r >> 1) & 3;
    }

    uint32_t acc[4][8][2];   // f16x2 accumulators (4 m-tiles x 8 n-tiles)
    #pragma unroll
    for (int a = 0; a < 4; a++)
        #pragma unroll
        for (int b = 0; b < 8; b++) { acc[a][b][0] = 0u; acc[a][b][1] = 0u; }

    // prologue: load chunk 0 into buffer 0
    #pragma unroll
    for (int p = 0; p < 4; p++) {
        CPA(aBase[0] + loff + p * 2048, Ag + (size_t)(p * 32) * D);
        if (!diag) CPA(bBase[0] + loff + p * 2048, Bg + (size_t)(p * 32) * D);
    }
    CPA_COMMIT();

    for (int kc = 0; kc < KSTEPS; kc++) {
        const int b = kc & 1;
        CPA_WAIT0();           // buffer b data arrived
        __syncthreads();       // visible to all; everyone done reading 1-b
        if (kc + 1 < KSTEPS) {
            const uint8_t* An = Ag + (kc + 1) * BK;
            const uint8_t* Bn = Bg + (kc + 1) * BK;
            #pragma unroll
            for (int p = 0; p < 4; p++) {
                CPA(aBase[1 - b] + loff + p * 2048, An + (size_t)(p * 32) * D);
                if (!diag) CPA(bBase[1 - b] + loff + p * 2048, Bn + (size_t)(p * 32) * D);
            }
            CPA_COMMIT();
        }

        #pragma unroll
        for (int ks = 0; ks < 2; ks++) {
            uint32_t af[4][4], bf[4][4];
            const uint32_t ca = 2 * ks + (lane >> 4);
            const uint32_t cb = 2 * ks + ((lane >> 3) & 1);
            #pragma unroll
            for (int mt = 0; mt < 4; mt++)
                LDX4(af[mt], aBase[b] + aoff[mt] + ((ca ^ asw[mt]) << 4));
            #pragma unroll
            for (int bt = 0; bt < 4; bt++)
                LDX4(bf[bt], bBase[b] + boff[bt] + ((cb ^ bsw[bt]) << 4));
            #pragma unroll
            for (int mt = 0; mt < 4; mt++)
                #pragma unroll
                for (int nt = 0; nt < 8; nt++)
                    mma_fp8_h(acc[mt][nt], af[mt], &bf[nt >> 1][(nt & 1) * 2]);
        }
    }
    __syncthreads();

    // ---------------- epilogue ----------------
    const float invT = 1.0f / Tptr[0];
    rowsum[tid] = 0.0f; rowsum[tid + 128] = 0.0f;
    colsum[tid] = 0.0f; colsum[tid + 128] = 0.0f;
    __syncthreads();

    const int g = lane >> 2, tig = lane & 3;
    int yj[8][2];
    #pragma unroll
    for (int nt = 0; nt < 8; nt++) {
        int j = j0 + wn + nt * 8 + 2 * tig;
        yj[nt][0] = g_lab[j];
        yj[nt][1] = g_lab[j + 1];
    }

    float ct[8][2] = {}, cb2[8][2] = {};   // per-thread column partials

    #pragma unroll
    for (int mt = 0; mt < 4; mt++) {
        #pragma unroll
        for (int h = 0; h < 2; h++) {
            const int li = wm + mt * 16 + h * 8 + g;
            const int i = i0 + li;
            const int yi = g_lab[i];
            float ts = 0.0f, bs = 0.0f;
            #pragma unroll
            for (int nt = 0; nt < 8; nt++) {
                float2 dv = __half22float2(
                    *reinterpret_cast<const __half2*>(&acc[mt][nt][h]));
                int j = j0 + wn + nt * 8 + 2 * tig;
                float f0 = __expf((dv.x - 1.0f) * invT);
                float f1 = __expf((dv.y - 1.0f) * invT);
                if (i == j) f0 = 0.0f;
                if (i == j + 1) f1 = 0.0f;
                bs += f0 + f1;
                cb2[nt][0] += f0;
                cb2[nt][1] += f1;
                if (yi == yj[nt][0]) { ts += f0; ct[nt][0] += f0; }
                if (yi == yj[nt][1]) { ts += f1; ct[nt][1] += f1; }
            }
            ts += __shfl_xor_sync(0xffffffffu, ts, 1);
            ts += __shfl_xor_sync(0xffffffffu, ts, 2);
            bs += __shfl_xor_sync(0xffffffffu, bs, 1);
            bs += __shfl_xor_sync(0xffffffffu, bs, 2);
            if (tig == 0) {
                atomicAdd(&rowsum[li * 2 + 0], ts);
                atomicAdd(&rowsum[li * 2 + 1], bs);
            }
        }
    }

    if (!diag) {
        #pragma unroll
        for (int nt = 0; nt < 8; nt++) {
            #pragma unroll
            for (int c = 0; c < 2; c++) {
                float vt = ct[nt][c], vb = cb2[nt][c];
                #pragma unroll
                for (int o = 4; o < 32; o <<= 1) {
                    vt += __shfl_xor_sync(0xffffffffu, vt, o);
                    vb += __shfl_xor_sync(0xffffffffu, vb, o);
                }
                if (g == 0) {
                    int lj = wn + nt * 8 + 2 * tig + c;
                    atomicAdd(&colsum[lj * 2 + 0], vt);
                    atomicAdd(&colsum[lj * 2 + 1], vb);
                }
            }
        }
    }

    __syncthreads();
    // 128 threads scatter 128 rows (and cols if off-diagonal)
    atomicAdd(&g_top[i0 + tid], rowsum[tid * 2 + 0]);
    atomicAdd(&g_bot[i0 + tid], rowsum[tid * 2 + 1]);
    if (!diag) {
        atomicAdd(&g_top[j0 + tid], colsum[tid * 2 + 0]);
        atomicAdd(&g_bot[j0 + tid], colsum[tid * 2 + 1]);
    }
}

// ---------------------------------------------------------------------------
// Loss: 32 blocks reduce log terms into g_loss; the LAST block to finish
// finalizes out[0] (threadfence + arrival counter; counter reset in labels).
// ---------------------------------------------------------------------------
__global__ void loss_part(float* __restrict__ out) {
    int i = blockIdx.x * 256 + threadIdx.x;
    float s = __logf((g_top[i] + 1e-9f) / g_bot[i]);
    #pragma unroll
    for (int o = 16; o; o >>= 1) s += __shfl_xor_sync(0xffffffffu, s, o);
    __shared__ float sred[8];
    __shared__ bool is_last;
    int lane = threadIdx.x & 31, w = threadIdx.x >> 5;
    if (lane == 0) sred[w] = s;
    __syncthreads();
    if (threadIdx.x == 0) {
        float s2 = 0.0f;
        #pragma unroll
        for (int k = 0; k < 8; k++) s2 += sred[k];
        atomicAdd(&g_loss, s2);
        __threadfence();
        unsigned int done = atomicAdd(&g_cnt, 1u);
        is_last = (done == gridDim.x - 1);
    }
    __syncthreads();
    if (is_last && threadIdx.x == 0)
        out[0] = -g_loss / (float)N;
}

extern "C" void kernel_launch(void* const* d_in, const int* in_sizes, int n_in,
                              void* d_out, int out_size) {
    const float* x = (const float*)d_in[0];
    const int*   y = (const int*)d_in[1];   // int32 view; layout auto-detected
    const float* T = (const float*)d_in[2];
    float* out = (float*)d_out;

    normalize_kernel<<<N / 8, 256>>>(x);    // 1
    labels_kernel<<<N / 256, 256>>>(y);     // 2
    snnl_fp8h<<<NTRI, 128>>>(T);            // 3
    loss_part<<<N / 256, 256>>>(out);       // 4
}